// round 2
// baseline (speedup 1.0000x reference)
#include <cuda_runtime.h>
#include <cuda_bf16.h>
#include <cstddef>

// y[token, k*128 + d] = (1/sqrt(32)) * sum_j H32[k,j] * x[token, j*128 + d]
// H32 = Sylvester Hadamard -> 5-stage fast Walsh-Hadamard butterfly.
//
// One block per token. Global traffic is pure sequential float4 bursts
// (512B per warp-request); the strided cross-head gather happens in SMEM
// (conflict-free: consecutive lanes -> consecutive banks).

#define HEADS 32
#define HEAD_DIM 128
#define HIDDEN 4096
#define VEC4 (HIDDEN / 4)   // 1024 float4 per row

__global__ __launch_bounds__(HEAD_DIM)
void fwht_cross_head_kernel(const float* __restrict__ x,
                            float* __restrict__ y,
                            int num_tokens)
{
    __shared__ float s[HIDDEN];

    const int token = blockIdx.x;
    if (token >= num_tokens) return;
    const int tid = threadIdx.x;  // 0..127 == d

    // Phase 1: fully-coalesced sequential vector load of the 16KB row.
    const float4* __restrict__ x4 = (const float4*)x + (size_t)token * VEC4;
    float4* __restrict__ s4 = (float4*)s;
    #pragma unroll
    for (int i = 0; i < 8; ++i) {
        s4[i * HEAD_DIM + tid] = __ldg(x4 + i * HEAD_DIM + tid);
    }
    __syncthreads();

    // Phase 2: gather the 32 head values for lane d from SMEM (conflict-free),
    // run the FWHT butterfly in registers, scatter back scaled.
    float v[HEADS];
    #pragma unroll
    for (int k = 0; k < HEADS; ++k) {
        v[k] = s[k * HEAD_DIM + tid];
    }

    #pragma unroll
    for (int st = 1; st < HEADS; st <<= 1) {
        #pragma unroll
        for (int i = 0; i < HEADS; ++i) {
            if ((i & st) == 0) {
                const float a = v[i];
                const float b = v[i + st];
                v[i]      = a + b;
                v[i + st] = a - b;
            }
        }
    }

    const float scale = 0.17677669529663687f;  // 1/sqrt(32)
    #pragma unroll
    for (int k = 0; k < HEADS; ++k) {
        s[k * HEAD_DIM + tid] = v[k] * scale;
    }
    __syncthreads();

    // Phase 3: fully-coalesced sequential vector store of the row.
    float4* __restrict__ y4 = (float4*)y + (size_t)token * VEC4;
    #pragma unroll
    for (int i = 0; i < 8; ++i) {
        y4[i * HEAD_DIM + tid] = s4[i * HEAD_DIM + tid];
    }
}

extern "C" void kernel_launch(void* const* d_in, const int* in_sizes, int n_in,
                              void* d_out, int out_size)
{
    const float* x = (const float*)d_in[0];
    // d_in[1] (had_K) is the deterministic 32x32 Sylvester Hadamard; the
    // butterfly implements it exactly, so it is not read on device.
    float* y = (float*)d_out;

    const int num_tokens = in_sizes[0] / HIDDEN;  // 16384

    fwht_cross_head_kernel<<<num_tokens, HEAD_DIM>>>(x, y, num_tokens);
}

// round 3
// speedup vs baseline: 1.1662x; 1.1662x over previous
#include <cuda_runtime.h>
#include <cuda_bf16.h>
#include <cstddef>

// y[token, k*128 + d] = (1/sqrt(32)) * sum_j H32[k,j] * x[token, j*128 + d]
// H32 = Sylvester Hadamard -> 5-stage fast Walsh-Hadamard butterfly.
//
// One WARP per token. Lane l owns dims [4l, 4l+3] via float4. Each thread
// keeps 32 float4 in registers (512B of loads in flight), butterflies across
// the head index element-wise, stores scaled. No smem, no barriers.

#define HEADS 32
#define HEAD_DIM 128
#define HIDDEN 4096
#define WARPS_PER_BLOCK 4

__global__ void fwht_cross_head_kernel(const float* __restrict__ x,
                                       float* __restrict__ y,
                                       int num_tokens)
{
    const int warp = threadIdx.x >> 5;
    const int lane = threadIdx.x & 31;
    const int token = blockIdx.x * WARPS_PER_BLOCK + warp;
    if (token >= num_tokens) return;

    // float4 view: one token row = 1024 float4; head k occupies [k*32, k*32+31].
    const float4* __restrict__ xr = (const float4*)x + (size_t)token * (HIDDEN / 4) + lane;
    float4* __restrict__ yr       = (float4*)y       + (size_t)token * (HIDDEN / 4) + lane;

    float4 v[HEADS];
    #pragma unroll
    for (int k = 0; k < HEADS; ++k) {
        v[k] = __ldg(xr + k * (HEAD_DIM / 4));
    }

    // 5-stage FWHT across the head index, element-wise on float4.
    #pragma unroll
    for (int s = 1; s < HEADS; s <<= 1) {
        #pragma unroll
        for (int i = 0; i < HEADS; ++i) {
            if ((i & s) == 0) {
                const float4 a = v[i];
                const float4 b = v[i + s];
                v[i].x = a.x + b.x;  v[i].y = a.y + b.y;
                v[i].z = a.z + b.z;  v[i].w = a.w + b.w;
                v[i + s].x = a.x - b.x;  v[i + s].y = a.y - b.y;
                v[i + s].z = a.z - b.z;  v[i + s].w = a.w - b.w;
            }
        }
    }

    const float scale = 0.17677669529663687f;  // 1/sqrt(32)
    #pragma unroll
    for (int k = 0; k < HEADS; ++k) {
        float4 o;
        o.x = v[k].x * scale;  o.y = v[k].y * scale;
        o.z = v[k].z * scale;  o.w = v[k].w * scale;
        yr[k * (HEAD_DIM / 4)] = o;
    }
}

extern "C" void kernel_launch(void* const* d_in, const int* in_sizes, int n_in,
                              void* d_out, int out_size)
{
    const float* x = (const float*)d_in[0];
    // d_in[1] (had_K) is the deterministic 32x32 Sylvester Hadamard; the
    // butterfly implements it exactly, so it is not read on device.
    float* y = (float*)d_out;

    const int num_tokens = in_sizes[0] / HIDDEN;  // 16384
    const int blocks = (num_tokens + WARPS_PER_BLOCK - 1) / WARPS_PER_BLOCK;

    fwht_cross_head_kernel<<<blocks, WARPS_PER_BLOCK * 32>>>(x, y, num_tokens);
}